// round 3
// baseline (speedup 1.0000x reference)
#include <cuda_runtime.h>
#include <math.h>

// Problem constants (fixed shapes)
#define B_    8
#define T_    1000
#define IN_   80
#define CONV_ 256
#define CCEP_ 222
#define HOP_  256
#define WIN_  512
#define NF_   1024
#define PAD_  401
#define ZLEN_ 256000

// ---------------- static device scratch (no allocations allowed) ----------------
__device__ float  g_bufA[B_ * T_ * CONV_];
__device__ float  g_bufB[B_ * T_ * CONV_];
__device__ float  g_cq  [B_ * T_ * CCEP_];
__device__ float  g_imp [B_ * T_ * NF_];
__device__ float  g_zw  [B_ * T_ * WIN_];
__device__ float2 g_tw  [512];

// ---------------- twiddle table: tw[k] = e^{-2*pi*i*k/1024} ----------------
__global__ void twiddle_kernel() {
    int k = threadIdx.x;           // 512 threads
    float s, c;
    sincosf(6.283185307179586f * (float)k * (1.0f / 1024.0f), &s, &c);
    g_tw[k] = make_float2(c, -s);
}

// ---------------- generic kernel-3 'same' conv1d (cross-correlation) ----------------
// y[b,t,o] = act( b[o] + sum_{i,k} x[b, t+k-1, cbase(o)+i] * W[o,i,k] )
template <int CIN, int COUT, int GROUPS, int OPER, int TTILE, bool RELU, bool QUEF>
__global__ void conv_kernel(const float* __restrict__ in, const float* __restrict__ W,
                            const float* __restrict__ bias, float* __restrict__ out) {
    constexpr int CING  = CIN / GROUPS;
    constexpr int GOUT  = COUT / GROUPS;
    constexpr int SROW  = CIN + (CIN >> 5) + 1;   // skewed row stride

    __shared__ float xs[(TTILE + 2) * SROW];

    const int b   = blockIdx.y;
    const int t0  = blockIdx.x * TTILE;
    const int tid = threadIdx.x;
    const int NT  = blockDim.x;

    // cooperative tile load (zero-padded in time)
    for (int idx = tid; idx < (TTILE + 2) * CIN; idx += NT) {
        int tt = idx / CIN;
        int c  = idx - tt * CIN;
        int t  = t0 + tt - 1;
        float v = 0.0f;
        if (t >= 0 && t < T_) v = in[(b * T_ + t) * CIN + c];
        xs[tt * SROW + c + (c >> 5)] = v;
    }
    __syncthreads();

    int o0 = tid * OPER;
    if (o0 >= COUT) return;

    float acc[OPER][TTILE];
#pragma unroll
    for (int u = 0; u < OPER; u++) {
        float bv = bias[o0 + u];
#pragma unroll
        for (int t = 0; t < TTILE; t++) acc[u][t] = bv;
    }

    const int g     = o0 / GOUT;
    const int cbase = g * CING;
    const float* Wp = W + (long)o0 * CING * 3;

    for (int i = 0; i < CING; i++) {
        int c  = cbase + i;
        int cp = c + (c >> 5);
        float xv[TTILE + 2];
#pragma unroll
        for (int tt = 0; tt < TTILE + 2; tt++) xv[tt] = xs[tt * SROW + cp];
#pragma unroll
        for (int u = 0; u < OPER; u++) {
            const float* wp = Wp + (u * CING + i) * 3;
            float w0 = wp[0], w1 = wp[1], w2 = wp[2];
#pragma unroll
            for (int t = 0; t < TTILE; t++)
                acc[u][t] += w0 * xv[t] + w1 * xv[t + 1] + w2 * xv[t + 2];
        }
    }

#pragma unroll
    for (int t = 0; t < TTILE; t++) {
        int tt = t0 + t;
        if (tt < T_) {
            float v[OPER];
#pragma unroll
            for (int u = 0; u < OPER; u++) {
                float val = acc[u][t];
                if (RELU) val = fmaxf(val, 0.0f);
                if (QUEF) {
                    int o = o0 + u;
                    float q = (o < COUT / 2) ? (float)(COUT / 2 - o)
                                             : (float)(o - COUT / 2 + 1);
                    val = val / q;
                }
                v[u] = val;
            }
            float* op = out + (long)(b * T_ + tt) * COUT + o0;
            if constexpr (OPER == 4) {
                *reinterpret_cast<float4*>(op) = make_float4(v[0], v[1], v[2], v[3]);
            } else if constexpr (OPER == 2) {
                *reinterpret_cast<float2*>(op) = make_float2(v[0], v[1]);
            } else {
#pragma unroll
                for (int u = 0; u < OPER; u++) op[u] = v[u];
            }
        }
    }
}

// ---------------- fused fwd-FFT -> 10^Re * e^{i Im} -> inv-FFT  (per (b,t) row) ----
// DIF forward (natural -> bit-reversed), pointwise in bit-reversed order (order-free),
// DIT inverse (bit-reversed -> natural). No permutation needed.
__global__ void fft_kernel() {
    __shared__ float2 a[1024];
    const int row = blockIdx.x;       // 0..7999
    const int tid = threadIdx.x;      // 256

    const float* src = g_cq + (long)row * CCEP_;
    for (int idx = tid; idx < 1024; idx += 256) {
        int j = idx - PAD_;
        float v = (j >= 0 && j < CCEP_) ? src[j] : 0.0f;
        a[idx] = make_float2(v, 0.0f);
    }
    __syncthreads();

    // forward DIF, stages m = 1024..2
#pragma unroll
    for (int s = 10; s >= 1; s--) {
        const int half = 1 << (s - 1);
#pragma unroll
        for (int r = 0; r < 2; r++) {
            int bf  = tid + (r << 8);
            int pos = bf & (half - 1);
            int i1  = ((bf >> (s - 1)) << s) + pos;
            int i2  = i1 + half;
            float2 x = a[i1], y = a[i2];
            float2 w = g_tw[pos << (10 - s)];
            float dr = x.x - y.x, di = x.y - y.y;
            a[i1] = make_float2(x.x + y.x, x.y + y.y);
            a[i2] = make_float2(dr * w.x - di * w.y, dr * w.y + di * w.x);
        }
        __syncthreads();
    }

    // pointwise: S = 10^{Re} * (cos Im, sin Im)
    for (int idx = tid; idx < 1024; idx += 256) {
        float2 y = a[idx];
        float mag = __expf(2.302585093f * y.x);
        float sn, cs;
        __sincosf(y.y, &sn, &cs);
        a[idx] = make_float2(mag * cs, mag * sn);
    }
    __syncthreads();

    // inverse DIT, stages m = 2..1024, conj twiddles
#pragma unroll
    for (int s = 1; s <= 10; s++) {
        const int half = 1 << (s - 1);
#pragma unroll
        for (int r = 0; r < 2; r++) {
            int bf  = tid + (r << 8);
            int pos = bf & (half - 1);
            int i1  = ((bf >> (s - 1)) << s) + pos;
            int i2  = i1 + half;
            float2 x = a[i1], y = a[i2];
            float2 w = g_tw[pos << (10 - s)];
            float tr = y.x * w.x + y.y * w.y;   // conj(w)*y
            float ti = y.y * w.x - y.x * w.y;
            a[i1] = make_float2(x.x + tr, x.y + ti);
            a[i2] = make_float2(x.x - tr, x.y - ti);
        }
        __syncthreads();
    }

    float* dst = g_imp + (long)row * NF_;
    for (int idx = tid; idx < 1024; idx += 256)
        dst[idx] = a[idx].x * (1.0f / 1024.0f);
}

// ---------------- direct correlation + Hann window ----------------
// corr[n] = sum_{j=0}^{511} frame[j] * imp[j + 511 - n],  n in [0,512)
// frame[j] = z[b, t*HOP + j - 255] (zero outside)
// Each of 64 threads computes 8 consecutive lags via a sliding register window.
__global__ void corr_kernel(const float* __restrict__ z) {
    __shared__ float fs[512];
    __shared__ float is[1152];        // skewed: phys = i + (i>>3)

    const int t = blockIdx.x, b = blockIdx.y;
    const int tid = threadIdx.x;      // 64

    const float* zb = z + (long)b * ZLEN_;
    for (int j = tid; j < 512; j += 64) {
        int src = t * HOP_ + j - 255;
        fs[j] = (src >= 0 && src < ZLEN_) ? zb[src] : 0.0f;
    }
    const float* ip = g_imp + (long)(b * T_ + t) * NF_;
    for (int j = tid; j < 1024; j += 64)
        is[j + (j >> 3)] = ip[j];
    __syncthreads();

    const int n0 = tid * 8;           // lags n0..n0+7
    float acc[8];
#pragma unroll
    for (int u = 0; u < 8; u++) acc[u] = 0.0f;

    // window invariant: entering step j, w[u] = imp[(j-1) + 511 - n0 - u]
    float w[8];
#pragma unroll
    for (int u = 0; u < 7; u++) { int e = 510 - n0 - u; w[u] = is[e + (e >> 3)]; }
    w[7] = 0.0f;

    const int ebase = 511 - n0;
    for (int j = 0; j < 512; j += 8) {
#pragma unroll
        for (int jj = 0; jj < 8; jj++) {
#pragma unroll
            for (int u = 7; u >= 1; u--) w[u] = w[u - 1];
            int e = ebase + j + jj;
            w[0] = is[e + (e >> 3)];
            float f = fs[j + jj];
#pragma unroll
            for (int u = 0; u < 8; u++) acc[u] += f * w[u];
        }
    }

    float* zr = g_zw + (long)(b * T_ + t) * WIN_;
#pragma unroll
    for (int u = 0; u < 8; u++) {
        int n = n0 + u;
        float wn = 0.5f * (1.0f - __cosf(0.0122718463f * (float)n)); // 2*pi/512
        zr[n] = acc[u] * wn;
    }
}

// ---------------- overlap-add with roll(r, 1) on the frame axis ----------------
// out[b, t*HOP + p] = zw[b,t,p] + zw[b,(t-1) mod T, HOP+p]
__global__ void ola_kernel(float* __restrict__ out) {
    const int t = blockIdx.x, b = blockIdx.y, p = threadIdx.x;   // 256 threads
    const int tp = (t == 0) ? (T_ - 1) : (t - 1);
    out[(long)(b * T_ + t) * HOP_ + p] =
        g_zw[(long)(b * T_ + t)  * WIN_ + p] +
        g_zw[(long)(b * T_ + tp) * WIN_ + HOP_ + p];
}

// ---------------- entry point ----------------
extern "C" void kernel_launch(void* const* d_in, const int* in_sizes, int n_in,
                              void* d_out, int out_size) {
    const float* x  = (const float*)d_in[0];
    const float* z  = (const float*)d_in[1];
    const float* W1 = (const float*)d_in[2];
    const float* b1 = (const float*)d_in[3];
    const float* W2 = (const float*)d_in[4];
    const float* b2 = (const float*)d_in[5];
    const float* W3 = (const float*)d_in[6];
    const float* b3 = (const float*)d_in[7];
    const float* W4 = (const float*)d_in[8];
    const float* b4 = (const float*)d_in[9];
    float* out = (float*)d_out;

    float *bufA, *bufB, *cq;
    cudaGetSymbolAddress((void**)&bufA, g_bufA);
    cudaGetSymbolAddress((void**)&bufB, g_bufB);
    cudaGetSymbolAddress((void**)&cq,   g_cq);

    twiddle_kernel<<<1, 512>>>();

    // conv1: 80 -> 256, groups 1, relu
    conv_kernel<80, 256, 1, 4, 16, true, false><<<dim3(63, 8), 64>>>(x, W1, b1, bufA);
    // conv2: 256 -> 256, groups 8, relu
    conv_kernel<256, 256, 8, 4, 16, true, false><<<dim3(63, 8), 64>>>(bufA, W2, b2, bufB);
    // conv3: 256 -> 256, groups 8, relu
    conv_kernel<256, 256, 8, 4, 16, true, false><<<dim3(63, 8), 64>>>(bufB, W3, b3, bufA);
    // conv4: 256 -> 222, groups 1, no relu, divide by quefrency
    conv_kernel<256, 222, 1, 2, 32, false, true><<<dim3(32, 8), 112>>>(bufA, W4, b4, cq);

    // cepstrum -> impulse response (one CTA per (b,t) row)
    fft_kernel<<<8000, 256>>>();

    // direct correlation + window
    corr_kernel<<<dim3(1000, 8), 64>>>(z);

    // overlap-add
    ola_kernel<<<dim3(1000, 8), 256>>>(out);
}

// round 4
// speedup vs baseline: 1.8393x; 1.8393x over previous
#include <cuda_runtime.h>
#include <math.h>

typedef unsigned long long ull;

// Problem constants (fixed shapes)
#define B_    8
#define T_    1000
#define IN_   80
#define CONV_ 256
#define CCEP_ 222
#define HOP_  256
#define WIN_  512
#define NF_   1024
#define PAD_  401
#define ZLEN_ 256000

// ---------------- static device scratch ----------------
__device__ float  g_bufA[B_ * T_ * CONV_];
__device__ float  g_bufB[B_ * T_ * CONV_];
__device__ float  g_cq  [B_ * T_ * CCEP_];
__device__ float  g_imp [B_ * T_ * NF_];
__device__ float  g_zw  [B_ * T_ * WIN_];
__device__ float2 g_tw  [512];
// transposed weights WT[(i*3+k)*COUT + o]
__device__ float  g_wT1[80  * 3 * 256];
__device__ float  g_wT2[32  * 3 * 256];
__device__ float  g_wT3[32  * 3 * 256];
__device__ float  g_wT4[256 * 3 * 222];

// ---------------- packed f32x2 helpers ----------------
__device__ __forceinline__ ull pack2(float lo, float hi) {
    ull r; asm("mov.b64 %0, {%1,%2};" : "=l"(r) : "f"(lo), "f"(hi)); return r;
}
__device__ __forceinline__ void unpack2(ull v, float& lo, float& hi) {
    asm("mov.b64 {%0,%1}, %2;" : "=f"(lo), "=f"(hi) : "l"(v));
}
__device__ __forceinline__ ull fma2(ull a, ull b, ull c) {
    ull d; asm("fma.rn.f32x2 %0, %1, %2, %3;" : "=l"(d) : "l"(a), "l"(b), "l"(c)); return d;
}

// ---------------- twiddle table: tw[k] = e^{-2*pi*i*k/1024} ----------------
__global__ void twiddle_kernel() {
    int k = threadIdx.x;           // 512 threads
    float s, c;
    sincosf(6.283185307179586f * (float)k * (1.0f / 1024.0f), &s, &c);
    g_tw[k] = make_float2(c, -s);
}

// ---------------- weight transpose: W[o][i][k] -> WT[(i*3+k)*COUT + o] ----------------
template <int CING, int COUT>
__global__ void wtrans_kernel(const float* __restrict__ W, float* __restrict__ WT) {
    int idx = blockIdx.x * 256 + threadIdx.x;
    if (idx >= COUT * CING * 3) return;
    int k = idx % 3;
    int i = (idx / 3) % CING;
    int o = idx / (3 * CING);
    WT[(i * 3 + k) * COUT + o] = W[idx];
}

// ---------------- conv1d 'same' (k=3), one output channel per thread ----------------
// xs stored time-contiguous per channel; time-pair packed FFMA2 math.
template <int CIN, int COUT, int GROUPS, bool RELU, bool QUEF>
__global__ void conv_kernel(const float* __restrict__ in, const float* __restrict__ WT,
                            const float* __restrict__ bias, float* __restrict__ out) {
    constexpr int CING  = CIN / GROUPS;
    constexpr int GOUT  = COUT / GROUPS;
    constexpr int TTILE = 16;
    constexpr int ROWS  = TTILE + 2;       // 18 floats = 72B per channel row (8B aligned)
    constexpr int PAIRS = TTILE / 2;       // 8

    __shared__ __align__(16) float xs[CIN * ROWS];

    const int b   = blockIdx.y;
    const int t0  = blockIdx.x * TTILE;
    const int tid = threadIdx.x;

    // cooperative tile load: xs[c*ROWS + tt] = in[b, t0+tt-1, c]  (coalesced over c)
    for (int idx = tid; idx < CIN * ROWS; idx += blockDim.x) {
        int tt = idx / CIN;
        int c  = idx - tt * CIN;
        int t  = t0 + tt - 1;
        float v = 0.0f;
        if (t >= 0 && t < T_) v = in[(b * T_ + t) * CIN + c];
        xs[c * ROWS + tt] = v;
    }
    __syncthreads();

    const int o = tid;
    if (o >= COUT) return;

    float bv = bias[o];
    ull binit = pack2(bv, bv);
    ull ac[PAIRS];
#pragma unroll
    for (int p = 0; p < PAIRS; p++) ac[p] = binit;

    const int cbase = (o / GOUT) * CING;
    const float* wp = WT + o;              // WT[(i*3+k)*COUT + o], coalesced over o

    for (int i = 0; i < CING; i++) {
        const ull* xr = reinterpret_cast<const ull*>(xs + (cbase + i) * ROWS);
        ull a[PAIRS + 1];
#pragma unroll
        for (int p = 0; p <= PAIRS; p++) a[p] = xr[p];   // LDS.64, warp-broadcast

        float lo[PAIRS + 1], hi[PAIRS + 1];
#pragma unroll
        for (int p = 0; p <= PAIRS; p++) unpack2(a[p], lo[p], hi[p]);

        float w0 = wp[(i * 3 + 0) * COUT];
        float w1 = wp[(i * 3 + 1) * COUT];
        float w2 = wp[(i * 3 + 2) * COUT];
        ull W0 = pack2(w0, w0), W1 = pack2(w1, w1), W2 = pack2(w2, w2);

#pragma unroll
        for (int p = 0; p < PAIRS; p++) {
            ull m = pack2(hi[p], lo[p + 1]);            // (xv[2p+1], xv[2p+2])
            ac[p] = fma2(W0, a[p],     ac[p]);          // (xv[2p],   xv[2p+1])
            ac[p] = fma2(W1, m,        ac[p]);
            ac[p] = fma2(W2, a[p + 1], ac[p]);          // (xv[2p+2], xv[2p+3])
        }
    }

    float rq = 1.0f;
    if (QUEF) {
        float q = (o < COUT / 2) ? (float)(COUT / 2 - o) : (float)(o - COUT / 2 + 1);
        rq = 1.0f / q;
    }

#pragma unroll
    for (int p = 0; p < PAIRS; p++) {
        float v0, v1;
        unpack2(ac[p], v0, v1);
        if (RELU) { v0 = fmaxf(v0, 0.0f); v1 = fmaxf(v1, 0.0f); }
        if (QUEF) { v0 *= rq; v1 *= rq; }
        int ta = t0 + 2 * p, tb = ta + 1;
        if (ta < T_) out[(long)(b * T_ + ta) * COUT + o] = v0;
        if (tb < T_) out[(long)(b * T_ + tb) * COUT + o] = v1;
    }
}

// ---------------- fused fwd-FFT -> 10^Re * e^{i Im} -> inv-FFT (per (b,t) row) ----
__global__ void fft_kernel() {
    __shared__ float2 a[1024];
    const int row = blockIdx.x;       // 0..7999
    const int tid = threadIdx.x;      // 256

    const float* src = g_cq + (long)row * CCEP_;
    for (int idx = tid; idx < 1024; idx += 256) {
        int j = idx - PAD_;
        float v = (j >= 0 && j < CCEP_) ? src[j] : 0.0f;
        a[idx] = make_float2(v, 0.0f);
    }
    __syncthreads();

    // forward DIF (natural -> bit-reversed)
#pragma unroll
    for (int s = 10; s >= 1; s--) {
        const int half = 1 << (s - 1);
#pragma unroll
        for (int r = 0; r < 2; r++) {
            int bf  = tid + (r << 8);
            int pos = bf & (half - 1);
            int i1  = ((bf >> (s - 1)) << s) + pos;
            int i2  = i1 + half;
            float2 x = a[i1], y = a[i2];
            float2 w = g_tw[pos << (10 - s)];
            float dr = x.x - y.x, di = x.y - y.y;
            a[i1] = make_float2(x.x + y.x, x.y + y.y);
            a[i2] = make_float2(dr * w.x - di * w.y, dr * w.y + di * w.x);
        }
        __syncthreads();
    }

    // pointwise: S = 10^{Re} * (cos Im, sin Im)  (bit-reversed order, elementwise)
    for (int idx = tid; idx < 1024; idx += 256) {
        float2 y = a[idx];
        float mag = __expf(2.302585093f * y.x);
        float sn, cs;
        __sincosf(y.y, &sn, &cs);
        a[idx] = make_float2(mag * cs, mag * sn);
    }
    __syncthreads();

    // inverse DIT (bit-reversed -> natural), conj twiddles
#pragma unroll
    for (int s = 1; s <= 10; s++) {
        const int half = 1 << (s - 1);
#pragma unroll
        for (int r = 0; r < 2; r++) {
            int bf  = tid + (r << 8);
            int pos = bf & (half - 1);
            int i1  = ((bf >> (s - 1)) << s) + pos;
            int i2  = i1 + half;
            float2 x = a[i1], y = a[i2];
            float2 w = g_tw[pos << (10 - s)];
            float tr = y.x * w.x + y.y * w.y;   // conj(w)*y
            float ti = y.y * w.x - y.x * w.y;
            a[i1] = make_float2(x.x + tr, x.y + ti);
            a[i2] = make_float2(x.x - tr, x.y - ti);
        }
        __syncthreads();
    }

    float* dst = g_imp + (long)row * NF_;
    for (int idx = tid; idx < 1024; idx += 256)
        dst[idx] = a[idx].x * (1.0f / 1024.0f);
}

// ---------------- direct correlation + Hann window (packed f32x2) ----------------
// corr[n] = sum_{j=0}^{511} frame[j] * imp[j + 511 - n],  n in [0,512)
__global__ void corr_kernel(const float* __restrict__ z) {
    __shared__ float fs[512];
    __shared__ float is[1152];        // skewed: phys = i + (i>>3)

    const int t = blockIdx.x, b = blockIdx.y;
    const int tid = threadIdx.x;      // 64

    const float* zb = z + (long)b * ZLEN_;
    for (int j = tid; j < 512; j += 64) {
        int src = t * HOP_ + j - 255;
        fs[j] = (src >= 0 && src < ZLEN_) ? zb[src] : 0.0f;
    }
    const float* ip = g_imp + (long)(b * T_ + t) * NF_;
    for (int j = tid; j < 1024; j += 64)
        is[j + (j >> 3)] = ip[j];
    __syncthreads();

    const int n0 = tid * 8;           // lags n0..n0+7
    ull ac2[4] = {0ULL, 0ULL, 0ULL, 0ULL};

    // window invariant: entering step j, w[u] = imp[(j-1) + 511 - n0 - u]
    float w[8];
#pragma unroll
    for (int u = 0; u < 7; u++) { int e = 510 - n0 - u; w[u] = is[e + (e >> 3)]; }
    w[7] = 0.0f;

    const int ebase = 511 - n0;
    for (int j = 0; j < 512; j += 8) {
#pragma unroll
        for (int jj = 0; jj < 8; jj++) {
#pragma unroll
            for (int u = 7; u >= 1; u--) w[u] = w[u - 1];
            int e = ebase + j + jj;
            w[0] = is[e + (e >> 3)];
            float f = fs[j + jj];
            ull fd = pack2(f, f);
            ac2[0] = fma2(fd, pack2(w[0], w[1]), ac2[0]);
            ac2[1] = fma2(fd, pack2(w[2], w[3]), ac2[1]);
            ac2[2] = fma2(fd, pack2(w[4], w[5]), ac2[2]);
            ac2[3] = fma2(fd, pack2(w[6], w[7]), ac2[3]);
        }
    }

    float* zr = g_zw + (long)(b * T_ + t) * WIN_;
#pragma unroll
    for (int q = 0; q < 4; q++) {
        float v0, v1;
        unpack2(ac2[q], v0, v1);
        int na = n0 + 2 * q, nb = na + 1;
        float wa = 0.5f * (1.0f - __cosf(0.0122718463f * (float)na)); // 2*pi/512
        float wb = 0.5f * (1.0f - __cosf(0.0122718463f * (float)nb));
        zr[na] = v0 * wa;
        zr[nb] = v1 * wb;
    }
}

// ---------------- overlap-add with roll(r, 1) on the frame axis ----------------
__global__ void ola_kernel(float* __restrict__ out) {
    const int t = blockIdx.x, b = blockIdx.y, p = threadIdx.x;   // 256 threads
    const int tp = (t == 0) ? (T_ - 1) : (t - 1);
    out[(long)(b * T_ + t) * HOP_ + p] =
        g_zw[(long)(b * T_ + t)  * WIN_ + p] +
        g_zw[(long)(b * T_ + tp) * WIN_ + HOP_ + p];
}

// ---------------- entry point ----------------
extern "C" void kernel_launch(void* const* d_in, const int* in_sizes, int n_in,
                              void* d_out, int out_size) {
    const float* x  = (const float*)d_in[0];
    const float* z  = (const float*)d_in[1];
    const float* W1 = (const float*)d_in[2];
    const float* b1 = (const float*)d_in[3];
    const float* W2 = (const float*)d_in[4];
    const float* b2 = (const float*)d_in[5];
    const float* W3 = (const float*)d_in[6];
    const float* b3 = (const float*)d_in[7];
    const float* W4 = (const float*)d_in[8];
    const float* b4 = (const float*)d_in[9];
    float* out = (float*)d_out;

    float *bufA, *bufB, *cq, *wt1, *wt2, *wt3, *wt4;
    cudaGetSymbolAddress((void**)&bufA, g_bufA);
    cudaGetSymbolAddress((void**)&bufB, g_bufB);
    cudaGetSymbolAddress((void**)&cq,   g_cq);
    cudaGetSymbolAddress((void**)&wt1,  g_wT1);
    cudaGetSymbolAddress((void**)&wt2,  g_wT2);
    cudaGetSymbolAddress((void**)&wt3,  g_wT3);
    cudaGetSymbolAddress((void**)&wt4,  g_wT4);

    twiddle_kernel<<<1, 512>>>();

    wtrans_kernel<80,  256><<<(80  * 3 * 256 + 255) / 256, 256>>>(W1, wt1);
    wtrans_kernel<32,  256><<<(32  * 3 * 256 + 255) / 256, 256>>>(W2, wt2);
    wtrans_kernel<32,  256><<<(32  * 3 * 256 + 255) / 256, 256>>>(W3, wt3);
    wtrans_kernel<256, 222><<<(256 * 3 * 222 + 255) / 256, 256>>>(W4, wt4);

    // conv1: 80 -> 256, groups 1, relu
    conv_kernel<80, 256, 1, true, false><<<dim3(63, 8), 256>>>(x, wt1, b1, bufA);
    // conv2: 256 -> 256, groups 8, relu
    conv_kernel<256, 256, 8, true, false><<<dim3(63, 8), 256>>>(bufA, wt2, b2, bufB);
    // conv3: 256 -> 256, groups 8, relu
    conv_kernel<256, 256, 8, true, false><<<dim3(63, 8), 256>>>(bufB, wt3, b3, bufA);
    // conv4: 256 -> 222, groups 1, no relu, quefrency divide
    conv_kernel<256, 222, 1, false, true><<<dim3(63, 8), 256>>>(bufA, wt4, b4, cq);

    // cepstrum -> impulse response (one CTA per (b,t) row)
    fft_kernel<<<8000, 256>>>();

    // direct correlation + window
    corr_kernel<<<dim3(1000, 8), 64>>>(z);

    // overlap-add
    ola_kernel<<<dim3(1000, 8), 256>>>(out);
}

// round 8
// speedup vs baseline: 1.8557x; 1.0089x over previous
#include <cuda_runtime.h>
#include <math.h>

typedef unsigned long long ull;

// Problem constants (fixed shapes)
#define B_    8
#define T_    1000
#define IN_   80
#define CONV_ 256
#define CCEP_ 222
#define HOP_  256
#define WIN_  512
#define NF_   1024
#define PAD_  401
#define ZLEN_ 256000

#define N1_ (80  * 3 * 256)
#define N2_ (32  * 3 * 256)
#define N3_ (32  * 3 * 256)
#define N4_ (256 * 3 * 222)

// ---------------- static device scratch ----------------
__device__ float  g_bufA[B_ * T_ * CONV_];
__device__ float  g_bufB[B_ * T_ * CONV_];
__device__ float  g_cq  [B_ * T_ * CCEP_];
__device__ float  g_imp [B_ * T_ * NF_];
__device__ float  g_zw  [B_ * T_ * WIN_];
__device__ float2 g_tw  [512];
// transposed + duplicated weights: WT2[(i*3+k)*COUT + o] = (w, w)
__device__ float2 g_wT1[N1_];
__device__ float2 g_wT2[N2_];
__device__ float2 g_wT3[N3_];
__device__ float2 g_wT4[N4_];

// ---------------- packed f32x2 helpers ----------------
__device__ __forceinline__ ull pack2(float lo, float hi) {
    ull r; asm("mov.b64 %0, {%1,%2};" : "=l"(r) : "f"(lo), "f"(hi)); return r;
}
__device__ __forceinline__ void unpack2(ull v, float& lo, float& hi) {
    asm("mov.b64 {%0,%1}, %2;" : "=f"(lo), "=f"(hi) : "l"(v));
}
__device__ __forceinline__ ull fma2(ull a, ull b, ull c) {
    ull d; asm("fma.rn.f32x2 %0, %1, %2, %3;" : "=l"(d) : "l"(a), "l"(b), "l"(c)); return d;
}
// (a.hi, b.lo)
__device__ __forceinline__ ull hilo(ull a, ull b) {
    float al, ah, bl, bh;
    unpack2(a, al, ah); unpack2(b, bl, bh);
    return pack2(ah, bl);
}

// ---------------- fused prep: twiddles + 4 weight transposes ----------------
__global__ void prep_kernel(const float* __restrict__ W1, const float* __restrict__ W2,
                            const float* __restrict__ W3, const float* __restrict__ W4) {
    int gid = blockIdx.x * 256 + threadIdx.x;
    if (gid < 512) {
        float s, c;
        sincosf(6.283185307179586f * (float)gid * (1.0f / 1024.0f), &s, &c);
        g_tw[gid] = make_float2(c, -s);
        return;
    }
    int id = gid - 512;
    if (id < N1_) {
        int k = id % 3, i = (id / 3) % 80, o = id / 240;
        float w = W1[id]; g_wT1[(i * 3 + k) * 256 + o] = make_float2(w, w); return;
    }
    id -= N1_;
    if (id < N2_) {
        int k = id % 3, i = (id / 3) % 32, o = id / 96;
        float w = W2[id]; g_wT2[(i * 3 + k) * 256 + o] = make_float2(w, w); return;
    }
    id -= N2_;
    if (id < N3_) {
        int k = id % 3, i = (id / 3) % 32, o = id / 96;
        float w = W3[id]; g_wT3[(i * 3 + k) * 256 + o] = make_float2(w, w); return;
    }
    id -= N3_;
    if (id < N4_) {
        int k = id % 3, i = (id / 3) % 256, o = id / 768;
        float w = W4[id]; g_wT4[(i * 3 + k) * 222 + o] = make_float2(w, w);
    }
}

// ---------------- conv1d 'same' (k=3), one output channel per thread ----------------
// xs0 row: xv[0..17] (xv[tt] = x[t0+tt-1]); xs1 row: xv[1..16] (pairs pre-shifted).
// Both rows stride 18 floats (72B) -> 8B-aligned pairs, 2-way STS conflicts max.
template <int CIN, int COUT, int GROUPS, bool RELU, bool QUEF>
__global__ void __launch_bounds__(256) conv_kernel(
        const float* __restrict__ in, const float2* __restrict__ WT2,
        const float* __restrict__ bias, float* __restrict__ out) {
    constexpr int CING  = CIN / GROUPS;
    constexpr int GOUT  = COUT / GROUPS;
    constexpr int TTILE = 16;
    constexpr int ROWS  = 18;
    constexpr int PAIRS = 8;

    __shared__ __align__(16) float xs0[CIN * ROWS];
    __shared__ __align__(16) float xs1[CIN * ROWS];

    const int b   = blockIdx.y;
    const int t0  = blockIdx.x * TTILE;
    const int tid = threadIdx.x;

    for (int idx = tid; idx < CIN * ROWS; idx += blockDim.x) {
        int tt = idx / CIN;
        int c  = idx - tt * CIN;
        int t  = t0 + tt - 1;
        float v = 0.0f;
        if (t >= 0 && t < T_) v = in[(b * T_ + t) * CIN + c];
        xs0[c * ROWS + tt] = v;
        if (tt >= 1 && tt <= 16) xs1[c * ROWS + (tt - 1)] = v;
    }
    __syncthreads();

    const int o = tid;
    if (o >= COUT) return;

    float bv = bias[o];
    ull binit = pack2(bv, bv);
    ull ac[PAIRS];
#pragma unroll
    for (int p = 0; p < PAIRS; p++) ac[p] = binit;

    const int cbase = (o / GOUT) * CING;
    const float2* wp = WT2 + o;

    for (int i = 0; i < CING; i++) {
        const ull* x0 = reinterpret_cast<const ull*>(xs0 + (cbase + i) * ROWS);
        const ull* x1 = reinterpret_cast<const ull*>(xs1 + (cbase + i) * ROWS);
        ull a0[PAIRS + 1], a1[PAIRS];
#pragma unroll
        for (int p = 0; p <= PAIRS; p++) a0[p] = x0[p];
#pragma unroll
        for (int p = 0; p < PAIRS; p++) a1[p] = x1[p];

        ull W0 = *reinterpret_cast<const ull*>(&wp[(i * 3 + 0) * COUT]);
        ull W1 = *reinterpret_cast<const ull*>(&wp[(i * 3 + 1) * COUT]);
        ull W2 = *reinterpret_cast<const ull*>(&wp[(i * 3 + 2) * COUT]);

#pragma unroll
        for (int p = 0; p < PAIRS; p++) {
            ac[p] = fma2(W0, a0[p],     ac[p]);
            ac[p] = fma2(W1, a1[p],     ac[p]);
            ac[p] = fma2(W2, a0[p + 1], ac[p]);
        }
    }

    float rq = 1.0f;
    if (QUEF) {
        float q = (o < COUT / 2) ? (float)(COUT / 2 - o) : (float)(o - COUT / 2 + 1);
        rq = 1.0f / q;
    }

#pragma unroll
    for (int p = 0; p < PAIRS; p++) {
        float v0, v1;
        unpack2(ac[p], v0, v1);
        if (RELU) { v0 = fmaxf(v0, 0.0f); v1 = fmaxf(v1, 0.0f); }
        if (QUEF) { v0 *= rq; v1 *= rq; }
        int ta = t0 + 2 * p, tb = ta + 1;
        if (ta < T_) out[(long)(b * T_ + ta) * COUT + o] = v0;
        if (tb < T_) out[(long)(b * T_ + tb) * COUT + o] = v1;
    }
}

// ---------------- fused fwd-FFT -> 10^Re * e^{i Im} -> inv-FFT ----------------
// Radix-4 rounds (2 radix-2 stages in registers per smem round).
// DIF forward (natural -> bit-reversed), pointwise elementwise, DIT inverse.
// Separate re/im arrays with idx+(idx>>5) skew: conflict-free at all strides.
#define FPHYS(i) ((i) + ((i) >> 5))

__global__ void __launch_bounds__(256) fft_kernel() {
    __shared__ float ar[1056], ai[1056];
    const int row = blockIdx.x;       // 0..7999
    const int tid = threadIdx.x;      // 256

    const float* src = g_cq + (long)row * CCEP_;
    for (int idx = tid; idx < 1024; idx += 256) {
        int j = idx - PAD_;
        float v = (j >= 0 && j < CCEP_) ? src[j] : 0.0f;
        int p = FPHYS(idx);
        ar[p] = v; ai[p] = 0.0f;
    }
    __syncthreads();

    // forward DIF rounds: stage pairs (10,9),(8,7),(6,5),(4,3),(2,1)
#pragma unroll
    for (int s = 10; s >= 2; s -= 2) {
        const int q   = 1 << (s - 2);
        const int pos = tid & (q - 1);
        const int blk = tid >> (s - 2);
        const int i0  = (blk << s) + pos;
        const int p0 = FPHYS(i0), p1 = FPHYS(i0 + q),
                  p2 = FPHYS(i0 + 2 * q), p3 = FPHYS(i0 + 3 * q);

        float x0r = ar[p0], x0i = ai[p0];
        float x1r = ar[p1], x1i = ai[p1];
        float x2r = ar[p2], x2i = ai[p2];
        float x3r = ar[p3], x3i = ai[p3];

        float2 wa = g_tw[pos << (10 - s)];
        float2 wb = g_tw[(pos + q) << (10 - s)];
        float2 wc = g_tw[pos << (11 - s)];

        // stage s: (x0,x2), (x1,x3)
        float t0r = x0r + x2r, t0i = x0i + x2i;
        float dr  = x0r - x2r, di  = x0i - x2i;
        float t2r = dr * wa.x - di * wa.y, t2i = dr * wa.y + di * wa.x;
        float t1r = x1r + x3r, t1i = x1i + x3i;
        dr = x1r - x3r; di = x1i - x3i;
        float t3r = dr * wb.x - di * wb.y, t3i = dr * wb.y + di * wb.x;

        // stage s-1: (t0,t1), (t2,t3), same twiddle wc
        float y0r = t0r + t1r, y0i = t0i + t1i;
        dr = t0r - t1r; di = t0i - t1i;
        float y1r = dr * wc.x - di * wc.y, y1i = dr * wc.y + di * wc.x;
        float y2r = t2r + t3r, y2i = t2i + t3i;
        dr = t2r - t3r; di = t2i - t3i;
        float y3r = dr * wc.x - di * wc.y, y3i = dr * wc.y + di * wc.x;

        __syncthreads();
        ar[p0] = y0r; ai[p0] = y0i;
        ar[p1] = y1r; ai[p1] = y1i;
        ar[p2] = y2r; ai[p2] = y2i;
        ar[p3] = y3r; ai[p3] = y3i;
        __syncthreads();
    }

    // pointwise: S = 10^{Re} * (cos Im, sin Im)   (bit-reversed order, elementwise)
    for (int idx = tid; idx < 1024; idx += 256) {
        int p = FPHYS(idx);
        float mag = __expf(2.302585093f * ar[p]);
        float sn, cs;
        __sincosf(ai[p], &sn, &cs);
        ar[p] = mag * cs; ai[p] = mag * sn;
    }
    __syncthreads();

    // inverse DIT rounds: stage pairs (1,2),(3,4),(5,6),(7,8),(9,10), conj twiddles
#pragma unroll
    for (int s = 1; s <= 9; s += 2) {
        const int q   = 1 << (s - 1);
        const int pos = tid & (q - 1);
        const int blk = tid >> (s - 1);
        const int i0  = (blk << (s + 1)) + pos;
        const int p0 = FPHYS(i0), p1 = FPHYS(i0 + q),
                  p2 = FPHYS(i0 + 2 * q), p3 = FPHYS(i0 + 3 * q);

        float x0r = ar[p0], x0i = ai[p0];
        float x1r = ar[p1], x1i = ai[p1];
        float x2r = ar[p2], x2i = ai[p2];
        float x3r = ar[p3], x3i = ai[p3];

        float2 wa = g_tw[pos << (10 - s)];
        float2 wb = g_tw[pos << (9 - s)];
        float2 wc = g_tw[(pos + q) << (9 - s)];

        // stage s: (x0,x1), (x2,x3), t = conj(wa)*x
        float tr = x1r * wa.x + x1i * wa.y, ti = x1i * wa.x - x1r * wa.y;
        float u0r = x0r + tr, u0i = x0i + ti;
        float u1r = x0r - tr, u1i = x0i - ti;
        tr = x3r * wa.x + x3i * wa.y; ti = x3i * wa.x - x3r * wa.y;
        float u2r = x2r + tr, u2i = x2i + ti;
        float u3r = x2r - tr, u3i = x2i - ti;

        // stage s+1: (u0,u2) w/ wb, (u1,u3) w/ wc
        tr = u2r * wb.x + u2i * wb.y; ti = u2i * wb.x - u2r * wb.y;
        float y0r = u0r + tr, y0i = u0i + ti;
        float y2r = u0r - tr, y2i = u0i - ti;
        tr = u3r * wc.x + u3i * wc.y; ti = u3i * wc.x - u3r * wc.y;
        float y1r = u1r + tr, y1i = u1i + ti;
        float y3r = u1r - tr, y3i = u1i - ti;

        __syncthreads();
        ar[p0] = y0r; ai[p0] = y0i;
        ar[p1] = y1r; ai[p1] = y1i;
        ar[p2] = y2r; ai[p2] = y2i;
        ar[p3] = y3r; ai[p3] = y3i;
        __syncthreads();
    }

    float* dst = g_imp + (long)row * NF_;
    for (int idx = tid; idx < 1024; idx += 256)
        dst[idx] = ar[FPHYS(idx)] * (1.0f / 1024.0f);
}

// ---------------- direct correlation + Hann window ----------------
// corr[n] = sum_j frame[j]*imp[j+511-n]. Accumulators packed over (even j, odd j);
// imp operands come from an aligned sliding pair-window.
// imp smem skew: phys = idx + 2*(idx>>3) keeps pairs adjacent & 8B-aligned, 2-wf loads.
#define IPHYS(i) ((i) + (((i) >> 3) << 1))

__global__ void __launch_bounds__(64) corr_kernel(const float* __restrict__ z) {
    __shared__ float fsf[512];
    __shared__ float is[1300];

    const int t = blockIdx.x, b = blockIdx.y;
    const int tid = threadIdx.x;      // 64

    const float* zb = z + (long)b * ZLEN_;
    for (int j = tid; j < 512; j += 64) {
        int src = t * HOP_ + j - 255;
        fsf[j] = (src >= 0 && src < ZLEN_) ? zb[src] : 0.0f;
    }
    const float* ip = g_imp + (long)(b * T_ + t) * NF_;
    for (int j = tid; j < 1024; j += 64)
        is[IPHYS(j)] = ip[j];
    for (int j = 1024 + tid; j < 1040; j += 64)
        is[IPHYS(j)] = 0.0f;
    __syncthreads();

    const ull* fs2 = reinterpret_cast<const ull*>(fsf);
    const int n0 = tid * 8;
    const int base0 = 504 - n0;          // window start (even)

    ull P[5];
#pragma unroll
    for (int m = 0; m < 5; m++) {
        int idx = base0 + 2 * m;
        P[m] = *reinterpret_cast<const ull*>(&is[IPHYS(idx)]);
    }
    ull acc[8];
#pragma unroll
    for (int u = 0; u < 8; u++) acc[u] = 0ULL;

#pragma unroll 16
    for (int js = 0; js < 256; js++) {
        ull fd = fs2[js];
        acc[7] = fma2(fd, P[0],           acc[7]);
        acc[6] = fma2(fd, hilo(P[0], P[1]), acc[6]);
        acc[5] = fma2(fd, P[1],           acc[5]);
        acc[4] = fma2(fd, hilo(P[1], P[2]), acc[4]);
        acc[3] = fma2(fd, P[2],           acc[3]);
        acc[2] = fma2(fd, hilo(P[2], P[3]), acc[2]);
        acc[1] = fma2(fd, P[3],           acc[1]);
        acc[0] = fma2(fd, hilo(P[3], P[4]), acc[0]);
        P[0] = P[1]; P[1] = P[2]; P[2] = P[3]; P[3] = P[4];
        int idx = base0 + 2 * js + 10;
        P[4] = *reinterpret_cast<const ull*>(&is[IPHYS(idx)]);
    }

    float* zr = g_zw + (long)(b * T_ + t) * WIN_;
#pragma unroll
    for (int u = 0; u < 8; u++) {
        float v0, v1;
        unpack2(acc[u], v0, v1);
        int n = n0 + u;
        float wn = 0.5f * (1.0f - __cosf(0.0122718463f * (float)n)); // 2*pi/512
        zr[n] = (v0 + v1) * wn;
    }
}

// ---------------- overlap-add with roll(r, 1) on the frame axis ----------------
__global__ void ola_kernel(float* __restrict__ out) {
    const int t = blockIdx.x, b = blockIdx.y, p = threadIdx.x;   // 256 threads
    const int tp = (t == 0) ? (T_ - 1) : (t - 1);
    out[(long)(b * T_ + t) * HOP_ + p] =
        g_zw[(long)(b * T_ + t)  * WIN_ + p] +
        g_zw[(long)(b * T_ + tp) * WIN_ + HOP_ + p];
}

// ---------------- entry point ----------------
extern "C" void kernel_launch(void* const* d_in, const int* in_sizes, int n_in,
                              void* d_out, int out_size) {
    const float* x  = (const float*)d_in[0];
    const float* z  = (const float*)d_in[1];
    const float* W1 = (const float*)d_in[2];
    const float* b1 = (const float*)d_in[3];
    const float* W2 = (const float*)d_in[4];
    const float* b2 = (const float*)d_in[5];
    const float* W3 = (const float*)d_in[6];
    const float* b3 = (const float*)d_in[7];
    const float* W4 = (const float*)d_in[8];
    const float* b4 = (const float*)d_in[9];
    float* out = (float*)d_out;

    float *bufA, *bufB, *cq;
    float2 *wt1, *wt2, *wt3, *wt4;
    cudaGetSymbolAddress((void**)&bufA, g_bufA);
    cudaGetSymbolAddress((void**)&bufB, g_bufB);
    cudaGetSymbolAddress((void**)&cq,   g_cq);
    cudaGetSymbolAddress((void**)&wt1,  g_wT1);
    cudaGetSymbolAddress((void**)&wt2,  g_wT2);
    cudaGetSymbolAddress((void**)&wt3,  g_wT3);
    cudaGetSymbolAddress((void**)&wt4,  g_wT4);

    // fused prep: twiddles + all weight transposes (512 + N1 + N2 + N3 + N4 = 281600)
    prep_kernel<<<1100, 256>>>(W1, W2, W3, W4);

    // conv1: 80 -> 256, groups 1, relu
    conv_kernel<80, 256, 1, true, false><<<dim3(63, 8), 256>>>(x, wt1, b1, bufA);
    // conv2: 256 -> 256, groups 8, relu
    conv_kernel<256, 256, 8, true, false><<<dim3(63, 8), 256>>>(bufA, wt2, b2, bufB);
    // conv3: 256 -> 256, groups 8, relu
    conv_kernel<256, 256, 8, true, false><<<dim3(63, 8), 256>>>(bufB, wt3, b3, bufA);
    // conv4: 256 -> 222, groups 1, no relu, quefrency divide
    conv_kernel<256, 222, 1, false, true><<<dim3(63, 8), 224>>>(bufA, wt4, b4, cq);

    // cepstrum -> impulse response (one CTA per (b,t) row)
    fft_kernel<<<8000, 256>>>();

    // direct correlation + window
    corr_kernel<<<dim3(1000, 8), 64>>>(z);

    // overlap-add
    ola_kernel<<<dim3(1000, 8), 256>>>(out);
}

// round 9
// speedup vs baseline: 1.8814x; 1.0139x over previous
#include <cuda_runtime.h>
#include <math.h>

typedef unsigned long long ull;

// Problem constants (fixed shapes)
#define B_    8
#define T_    1000
#define IN_   80
#define CONV_ 256
#define CCEP_ 222
#define HOP_  256
#define WIN_  512
#define NF_   1024
#define PAD_  401
#define ZLEN_ 256000

#define N1_ (80  * 3 * 256)
#define N2_ (32  * 3 * 256)
#define N3_ (32  * 3 * 256)
#define N4_ (256 * 3 * 222)

// ---------------- static device scratch ----------------
__device__ float  g_bufA[B_ * T_ * CONV_];
__device__ float  g_bufB[B_ * T_ * CONV_];
__device__ float  g_cq  [B_ * T_ * CCEP_];
__device__ float  g_imp [B_ * T_ * NF_];
__device__ float  g_zw  [B_ * T_ * WIN_];
__device__ float2 g_tw  [512];
// transposed + duplicated weights: WT2[(i*3+k)*COUT + o] = (w, w)
__device__ float2 g_wT1[N1_];
__device__ float2 g_wT2[N2_];
__device__ float2 g_wT3[N3_];
__device__ float2 g_wT4[N4_];

// ---------------- packed f32x2 helpers ----------------
__device__ __forceinline__ ull pack2(float lo, float hi) {
    ull r; asm("mov.b64 %0, {%1,%2};" : "=l"(r) : "f"(lo), "f"(hi)); return r;
}
__device__ __forceinline__ void unpack2(ull v, float& lo, float& hi) {
    asm("mov.b64 {%0,%1}, %2;" : "=f"(lo), "=f"(hi) : "l"(v));
}
__device__ __forceinline__ ull fma2(ull a, ull b, ull c) {
    ull d; asm("fma.rn.f32x2 %0, %1, %2, %3;" : "=l"(d) : "l"(a), "l"(b), "l"(c)); return d;
}
// (a.hi, b.lo)
__device__ __forceinline__ ull hilo(ull a, ull b) {
    float al, ah, bl, bh;
    unpack2(a, al, ah); unpack2(b, bl, bh);
    return pack2(ah, bl);
}

// ---------------- fused prep: twiddles + 4 weight transposes ----------------
__global__ void prep_kernel(const float* __restrict__ W1, const float* __restrict__ W2,
                            const float* __restrict__ W3, const float* __restrict__ W4) {
    int gid = blockIdx.x * 256 + threadIdx.x;
    if (gid < 512) {
        float s, c;
        sincosf(6.283185307179586f * (float)gid * (1.0f / 1024.0f), &s, &c);
        g_tw[gid] = make_float2(c, -s);
        return;
    }
    int id = gid - 512;
    if (id < N1_) {
        int k = id % 3, i = (id / 3) % 80, o = id / 240;
        float w = W1[id]; g_wT1[(i * 3 + k) * 256 + o] = make_float2(w, w); return;
    }
    id -= N1_;
    if (id < N2_) {
        int k = id % 3, i = (id / 3) % 32, o = id / 96;
        float w = W2[id]; g_wT2[(i * 3 + k) * 256 + o] = make_float2(w, w); return;
    }
    id -= N2_;
    if (id < N3_) {
        int k = id % 3, i = (id / 3) % 32, o = id / 96;
        float w = W3[id]; g_wT3[(i * 3 + k) * 256 + o] = make_float2(w, w); return;
    }
    id -= N3_;
    if (id < N4_) {
        int k = id % 3, i = (id / 3) % 256, o = id / 768;
        float w = W4[id]; g_wT4[(i * 3 + k) * 222 + o] = make_float2(w, w);
    }
}

// ---------------- conv1d 'same' (k=3), 2 output channels per thread ----------------
// 256 threads = 128 o-pairs x 2 time-halves; CTA covers 32 time steps.
// Single input tile xs[c][tt], tt in [0,34); middle-tap pairs built via hilo().
// Weight pair (o, o+1) loaded as one LDG.128 from the dup-(w,w) layout.
template <int CIN, int COUT, int GROUPS, bool RELU, bool QUEF>
__global__ void __launch_bounds__(256) conv_kernel(
        const float* __restrict__ in, const float2* __restrict__ WT2,
        const float* __restrict__ bias, float* __restrict__ out) {
    constexpr int CING  = CIN / GROUPS;
    constexpr int GOUT  = COUT / GROUPS;
    constexpr int TCTA  = 32;
    constexpr int ROWS  = TCTA + 2;       // 34 floats per channel row (8B-aligned pairs)
    constexpr int PAIRS = 8;              // per thread: 16 time steps

    __shared__ __align__(16) float xs[CIN * ROWS];

    const int b    = blockIdx.y;
    const int T0   = blockIdx.x * TCTA;
    const int tid  = threadIdx.x;
    const int half = tid >> 7;            // 0 or 1
    const int op   = tid & 127;           // o-pair index
    const int o    = op * 2;

    // cooperative tile load: xs[c*ROWS + tt] = in[b, T0+tt-1, c]
    for (int idx = tid; idx < CIN * ROWS; idx += 256) {
        int tt = idx / CIN;
        int c  = idx - tt * CIN;
        int t  = T0 + tt - 1;
        float v = 0.0f;
        if (t >= 0 && t < T_) v = in[(b * T_ + t) * CIN + c];
        xs[c * ROWS + tt] = v;
    }
    __syncthreads();

    if (o >= COUT) return;                // conv4: op in [111,128) idle

    const float bv0 = bias[o], bv1 = bias[o + 1];
    ull ac0[PAIRS], ac1[PAIRS];
    const ull bi0 = pack2(bv0, bv0), bi1 = pack2(bv1, bv1);
#pragma unroll
    for (int p = 0; p < PAIRS; p++) { ac0[p] = bi0; ac1[p] = bi1; }

    const int cbase = (o / GOUT) * CING;
    const float2* wrow = WT2 + o;
    const int toff = half * (TCTA / 2);   // 0 or 16

    for (int i = 0; i < CING; i++) {
        const ull* xr = reinterpret_cast<const ull*>(xs + (cbase + i) * ROWS + toff);
        ull a0[PAIRS + 1];
#pragma unroll
        for (int p = 0; p <= PAIRS; p++) a0[p] = xr[p];     // 9 LDS.64, warp-broadcast
        ull mid[PAIRS];
#pragma unroll
        for (int p = 0; p < PAIRS; p++) mid[p] = hilo(a0[p], a0[p + 1]);

        ulonglong2 w0 = *reinterpret_cast<const ulonglong2*>(wrow + (i * 3 + 0) * COUT);
        ulonglong2 w1 = *reinterpret_cast<const ulonglong2*>(wrow + (i * 3 + 1) * COUT);
        ulonglong2 w2 = *reinterpret_cast<const ulonglong2*>(wrow + (i * 3 + 2) * COUT);

#pragma unroll
        for (int p = 0; p < PAIRS; p++) {
            ac0[p] = fma2(w0.x, a0[p],     ac0[p]);
            ac0[p] = fma2(w1.x, mid[p],    ac0[p]);
            ac0[p] = fma2(w2.x, a0[p + 1], ac0[p]);
            ac1[p] = fma2(w0.y, a0[p],     ac1[p]);
            ac1[p] = fma2(w1.y, mid[p],    ac1[p]);
            ac1[p] = fma2(w2.y, a0[p + 1], ac1[p]);
        }
    }

    float rq0 = 1.0f, rq1 = 1.0f;
    if (QUEF) {
        float q0 = (o     < COUT / 2) ? (float)(COUT / 2 - o)     : (float)(o     - COUT / 2 + 1);
        float q1 = (o + 1 < COUT / 2) ? (float)(COUT / 2 - o - 1) : (float)(o + 1 - COUT / 2 + 1);
        rq0 = 1.0f / q0; rq1 = 1.0f / q1;
    }

#pragma unroll
    for (int p = 0; p < PAIRS; p++) {
        float v00, v01, v10, v11;
        unpack2(ac0[p], v00, v01);        // channel o,   times (ta, ta+1)
        unpack2(ac1[p], v10, v11);        // channel o+1
        if (RELU) {
            v00 = fmaxf(v00, 0.0f); v01 = fmaxf(v01, 0.0f);
            v10 = fmaxf(v10, 0.0f); v11 = fmaxf(v11, 0.0f);
        }
        if (QUEF) { v00 *= rq0; v01 *= rq0; v10 *= rq1; v11 *= rq1; }
        int ta = T0 + toff + 2 * p, tb = ta + 1;
        if (ta < T_)
            *reinterpret_cast<float2*>(out + (long)(b * T_ + ta) * COUT + o) = make_float2(v00, v10);
        if (tb < T_)
            *reinterpret_cast<float2*>(out + (long)(b * T_ + tb) * COUT + o) = make_float2(v01, v11);
    }
}

// ---------------- fused fwd-FFT -> 10^Re * e^{i Im} -> inv-FFT ----------------
// Radix-4 rounds (2 radix-2 stages in registers per smem round).
// DIF forward (natural -> bit-reversed), pointwise elementwise, DIT inverse.
#define FPHYS(i) ((i) + ((i) >> 5))

__global__ void __launch_bounds__(256) fft_kernel() {
    __shared__ float ar[1056], ai[1056];
    const int row = blockIdx.x;       // 0..7999
    const int tid = threadIdx.x;      // 256

    const float* src = g_cq + (long)row * CCEP_;
    for (int idx = tid; idx < 1024; idx += 256) {
        int j = idx - PAD_;
        float v = (j >= 0 && j < CCEP_) ? src[j] : 0.0f;
        int p = FPHYS(idx);
        ar[p] = v; ai[p] = 0.0f;
    }
    __syncthreads();

    // forward DIF rounds: stage pairs (10,9),(8,7),(6,5),(4,3),(2,1)
#pragma unroll
    for (int s = 10; s >= 2; s -= 2) {
        const int q   = 1 << (s - 2);
        const int pos = tid & (q - 1);
        const int blk = tid >> (s - 2);
        const int i0  = (blk << s) + pos;
        const int p0 = FPHYS(i0), p1 = FPHYS(i0 + q),
                  p2 = FPHYS(i0 + 2 * q), p3 = FPHYS(i0 + 3 * q);

        float x0r = ar[p0], x0i = ai[p0];
        float x1r = ar[p1], x1i = ai[p1];
        float x2r = ar[p2], x2i = ai[p2];
        float x3r = ar[p3], x3i = ai[p3];

        float2 wa = g_tw[pos << (10 - s)];
        float2 wb = g_tw[(pos + q) << (10 - s)];
        float2 wc = g_tw[pos << (11 - s)];

        float t0r = x0r + x2r, t0i = x0i + x2i;
        float dr  = x0r - x2r, di  = x0i - x2i;
        float t2r = dr * wa.x - di * wa.y, t2i = dr * wa.y + di * wa.x;
        float t1r = x1r + x3r, t1i = x1i + x3i;
        dr = x1r - x3r; di = x1i - x3i;
        float t3r = dr * wb.x - di * wb.y, t3i = dr * wb.y + di * wb.x;

        float y0r = t0r + t1r, y0i = t0i + t1i;
        dr = t0r - t1r; di = t0i - t1i;
        float y1r = dr * wc.x - di * wc.y, y1i = dr * wc.y + di * wc.x;
        float y2r = t2r + t3r, y2i = t2i + t3i;
        dr = t2r - t3r; di = t2i - t3i;
        float y3r = dr * wc.x - di * wc.y, y3i = dr * wc.y + di * wc.x;

        __syncthreads();
        ar[p0] = y0r; ai[p0] = y0i;
        ar[p1] = y1r; ai[p1] = y1i;
        ar[p2] = y2r; ai[p2] = y2i;
        ar[p3] = y3r; ai[p3] = y3i;
        __syncthreads();
    }

    // pointwise: S = 10^{Re} * (cos Im, sin Im)
    for (int idx = tid; idx < 1024; idx += 256) {
        int p = FPHYS(idx);
        float mag = __expf(2.302585093f * ar[p]);
        float sn, cs;
        __sincosf(ai[p], &sn, &cs);
        ar[p] = mag * cs; ai[p] = mag * sn;
    }
    __syncthreads();

    // inverse DIT rounds: stage pairs (1,2),(3,4),(5,6),(7,8),(9,10), conj twiddles
#pragma unroll
    for (int s = 1; s <= 9; s += 2) {
        const int q   = 1 << (s - 1);
        const int pos = tid & (q - 1);
        const int blk = tid >> (s - 1);
        const int i0  = (blk << (s + 1)) + pos;
        const int p0 = FPHYS(i0), p1 = FPHYS(i0 + q),
                  p2 = FPHYS(i0 + 2 * q), p3 = FPHYS(i0 + 3 * q);

        float x0r = ar[p0], x0i = ai[p0];
        float x1r = ar[p1], x1i = ai[p1];
        float x2r = ar[p2], x2i = ai[p2];
        float x3r = ar[p3], x3i = ai[p3];

        float2 wa = g_tw[pos << (10 - s)];
        float2 wb = g_tw[pos << (9 - s)];
        float2 wc = g_tw[(pos + q) << (9 - s)];

        float tr = x1r * wa.x + x1i * wa.y, ti = x1i * wa.x - x1r * wa.y;
        float u0r = x0r + tr, u0i = x0i + ti;
        float u1r = x0r - tr, u1i = x0i - ti;
        tr = x3r * wa.x + x3i * wa.y; ti = x3i * wa.x - x3r * wa.y;
        float u2r = x2r + tr, u2i = x2i + ti;
        float u3r = x2r - tr, u3i = x2i - ti;

        tr = u2r * wb.x + u2i * wb.y; ti = u2i * wb.x - u2r * wb.y;
        float y0r = u0r + tr, y0i = u0i + ti;
        float y2r = u0r - tr, y2i = u0i - ti;
        tr = u3r * wc.x + u3i * wc.y; ti = u3i * wc.x - u3r * wc.y;
        float y1r = u1r + tr, y1i = u1i + ti;
        float y3r = u1r - tr, y3i = u1i - ti;

        __syncthreads();
        ar[p0] = y0r; ai[p0] = y0i;
        ar[p1] = y1r; ai[p1] = y1i;
        ar[p2] = y2r; ai[p2] = y2i;
        ar[p3] = y3r; ai[p3] = y3i;
        __syncthreads();
    }

    float* dst = g_imp + (long)row * NF_;
    for (int idx = tid; idx < 1024; idx += 256)
        dst[idx] = ar[FPHYS(idx)] * (1.0f / 1024.0f);
}

// ---------------- direct correlation + Hann window ----------------
#define IPHYS(i) ((i) + (((i) >> 3) << 1))

__global__ void __launch_bounds__(64) corr_kernel(const float* __restrict__ z) {
    __shared__ float fsf[512];
    __shared__ float is[1300];

    const int t = blockIdx.x, b = blockIdx.y;
    const int tid = threadIdx.x;      // 64

    const float* zb = z + (long)b * ZLEN_;
    for (int j = tid; j < 512; j += 64) {
        int src = t * HOP_ + j - 255;
        fsf[j] = (src >= 0 && src < ZLEN_) ? zb[src] : 0.0f;
    }
    const float* ip = g_imp + (long)(b * T_ + t) * NF_;
    for (int j = tid; j < 1024; j += 64)
        is[IPHYS(j)] = ip[j];
    for (int j = 1024 + tid; j < 1040; j += 64)
        is[IPHYS(j)] = 0.0f;
    __syncthreads();

    const ull* fs2 = reinterpret_cast<const ull*>(fsf);
    const int n0 = tid * 8;
    const int base0 = 504 - n0;

    ull P[5];
#pragma unroll
    for (int m = 0; m < 5; m++) {
        int idx = base0 + 2 * m;
        P[m] = *reinterpret_cast<const ull*>(&is[IPHYS(idx)]);
    }
    ull acc[8];
#pragma unroll
    for (int u = 0; u < 8; u++) acc[u] = 0ULL;

#pragma unroll 16
    for (int js = 0; js < 256; js++) {
        ull fd = fs2[js];
        acc[7] = fma2(fd, P[0],             acc[7]);
        acc[6] = fma2(fd, hilo(P[0], P[1]), acc[6]);
        acc[5] = fma2(fd, P[1],             acc[5]);
        acc[4] = fma2(fd, hilo(P[1], P[2]), acc[4]);
        acc[3] = fma2(fd, P[2],             acc[3]);
        acc[2] = fma2(fd, hilo(P[2], P[3]), acc[2]);
        acc[1] = fma2(fd, P[3],             acc[1]);
        acc[0] = fma2(fd, hilo(P[3], P[4]), acc[0]);
        P[0] = P[1]; P[1] = P[2]; P[2] = P[3]; P[3] = P[4];
        int idx = base0 + 2 * js + 10;
        P[4] = *reinterpret_cast<const ull*>(&is[IPHYS(idx)]);
    }

    float* zr = g_zw + (long)(b * T_ + t) * WIN_;
#pragma unroll
    for (int u = 0; u < 8; u++) {
        float v0, v1;
        unpack2(acc[u], v0, v1);
        int n = n0 + u;
        float wn = 0.5f * (1.0f - __cosf(0.0122718463f * (float)n)); // 2*pi/512
        zr[n] = (v0 + v1) * wn;
    }
}

// ---------------- overlap-add with roll(r, 1) on the frame axis ----------------
__global__ void ola_kernel(float* __restrict__ out) {
    const int t = blockIdx.x, b = blockIdx.y, p = threadIdx.x;   // 256 threads
    const int tp = (t == 0) ? (T_ - 1) : (t - 1);
    out[(long)(b * T_ + t) * HOP_ + p] =
        g_zw[(long)(b * T_ + t)  * WIN_ + p] +
        g_zw[(long)(b * T_ + tp) * WIN_ + HOP_ + p];
}

// ---------------- entry point ----------------
extern "C" void kernel_launch(void* const* d_in, const int* in_sizes, int n_in,
                              void* d_out, int out_size) {
    const float* x  = (const float*)d_in[0];
    const float* z  = (const float*)d_in[1];
    const float* W1 = (const float*)d_in[2];
    const float* b1 = (const float*)d_in[3];
    const float* W2 = (const float*)d_in[4];
    const float* b2 = (const float*)d_in[5];
    const float* W3 = (const float*)d_in[6];
    const float* b3 = (const float*)d_in[7];
    const float* W4 = (const float*)d_in[8];
    const float* b4 = (const float*)d_in[9];
    float* out = (float*)d_out;

    float *bufA, *bufB, *cq;
    float2 *wt1, *wt2, *wt3, *wt4;
    cudaGetSymbolAddress((void**)&bufA, g_bufA);
    cudaGetSymbolAddress((void**)&bufB, g_bufB);
    cudaGetSymbolAddress((void**)&cq,   g_cq);
    cudaGetSymbolAddress((void**)&wt1,  g_wT1);
    cudaGetSymbolAddress((void**)&wt2,  g_wT2);
    cudaGetSymbolAddress((void**)&wt3,  g_wT3);
    cudaGetSymbolAddress((void**)&wt4,  g_wT4);

    // fused prep: twiddles + all weight transposes
    prep_kernel<<<1100, 256>>>(W1, W2, W3, W4);

    // 32 time steps per CTA: ceil(1000/32) = 32 blocks in x
    // conv1: 80 -> 256, groups 1, relu
    conv_kernel<80, 256, 1, true, false><<<dim3(32, 8), 256>>>(x, wt1, b1, bufA);
    // conv2: 256 -> 256, groups 8, relu
    conv_kernel<256, 256, 8, true, false><<<dim3(32, 8), 256>>>(bufA, wt2, b2, bufB);
    // conv3: 256 -> 256, groups 8, relu
    conv_kernel<256, 256, 8, true, false><<<dim3(32, 8), 256>>>(bufB, wt3, b3, bufA);
    // conv4: 256 -> 222, groups 1, no relu, quefrency divide
    conv_kernel<256, 222, 1, false, true><<<dim3(32, 8), 256>>>(bufA, wt4, b4, cq);

    // cepstrum -> impulse response (one CTA per (b,t) row)
    fft_kernel<<<8000, 256>>>();

    // direct correlation + window
    corr_kernel<<<dim3(1000, 8), 64>>>(z);

    // overlap-add
    ola_kernel<<<dim3(1000, 8), 256>>>(out);
}